// round 6
// baseline (speedup 1.0000x reference)
#include <cuda_runtime.h>
#include <cuda_fp16.h>
#include <math.h>

#define NN 100000
#define EE 1600000
#define CC 128
#define CAP 96
#define OUTC 10

// ---- scratch (device globals: no allocation allowed) ----
__device__ __half g_Yh[(size_t)NN * CC];      // x @ W_rel, fp16 (25.6 MB)
__device__ float  g_R0[(size_t)NN * CC];      // ping
__device__ float  g_R1[(size_t)NN * CC];      // pong
__device__ int    g_cnt[NN];
__device__ __align__(16) uint2 g_bucket[(size_t)NN * CAP]; // {src, w-bits}

// ---------------------------------------------------------------------------
// Edge preprocessing: bucket edges by destination
// ---------------------------------------------------------------------------
__global__ void k_zero_cnt() {
    int i = blockIdx.x * blockDim.x + threadIdx.x;
    if (i < NN) g_cnt[i] = 0;
}

__global__ void k_bucket(const int* __restrict__ src, const int* __restrict__ dst,
                         const float* __restrict__ ew) {
    int e = blockIdx.x * blockDim.x + threadIdx.x;
    if (e >= EE) return;
    int d = dst[e];
    int s = atomicAdd(&g_cnt[d], 1);
    if (s < CAP)
        g_bucket[(size_t)d * CAP + s] = make_uint2((unsigned)src[e], __float_as_uint(ew[e]));
}

// ---------------------------------------------------------------------------
// 3x-bf16 tensor-core dual GEMM, split hoisted to staging.
//   smem planes (bf16, stored as u32 words):
//     Ah/Al: [128 rows][AW=68 words]  (A pre-split, row-major, K contiguous)
//     Bh/Bl: [64 n-rows][BW=68 words] (B pre-split, TRANSPOSED: n-major, K contig)
//   Mainloop: pure LDS.32 (conflict-free: bank = 4*gr + tg + const) + HMMA.
//   3 mma passes: Ah*Bl + Al*Bh + Ah*Bh (drop Al*Bl ~ 2^-16).
// ---------------------------------------------------------------------------
#define AW 68                       // words per A row (136 bf16, pad 8)
#define BW 68                       // words per Bt row
#define A_WORDS (128 * AW)          // 8704
#define B_WORDS (64 * BW)           // 4352
#define GEMM_SMEM ((2 * A_WORDS + 2 * B_WORDS) * 4)   // 104448 B

// pack two consecutive-k fp32 values into bf16x2 hi + bf16x2 lo (residual)
__device__ __forceinline__ void split2_bf16(float x0, float x1,
                                            unsigned& h, unsigned& l) {
    asm("cvt.rn.bf16x2.f32 %0, %1, %2;" : "=r"(h) : "f"(x1), "f"(x0));
    float h0 = __uint_as_float(h << 16);
    float h1 = __uint_as_float(h & 0xffff0000u);
    float l0 = x0 - h0, l1 = x1 - h1;
    asm("cvt.rn.bf16x2.f32 %0, %1, %2;" : "=r"(l) : "f"(l1), "f"(l0));
}

__device__ __forceinline__ void mma_bf16(float4& d,
                                         const unsigned a[4], const unsigned b[2]) {
    asm volatile(
        "mma.sync.aligned.m16n8k16.row.col.f32.bf16.bf16.f32 "
        "{%0,%1,%2,%3}, {%4,%5,%6,%7}, {%8,%9}, {%0,%1,%2,%3};\n"
        : "+f"(d.x), "+f"(d.y), "+f"(d.z), "+f"(d.w)
        : "r"(a[0]), "r"(a[1]), "r"(a[2]), "r"(a[3]), "r"(b[0]), "r"(b[1]));
}

__global__ __launch_bounds__(256, 1)
void k_gemm_dual(const float* __restrict__ Xext,
                 int in_sel,              // 0: Xext, 1: g_R0 (ReLU), 2: g_R1 (ReLU)
                 int out_sel,             // 0: R=g_R0, 1: R=g_R1
                 const float* __restrict__ Wrel,
                 const float* __restrict__ Wroot,
                 const float* __restrict__ bias)
{
    extern __shared__ unsigned sw[];
    unsigned* Ah = sw;
    unsigned* Al = sw + A_WORDS;
    unsigned* Bh = sw + 2 * A_WORDS;
    unsigned* Bl = sw + 2 * A_WORDS + B_WORDS;

    const float* X = (in_sel == 0) ? Xext : (in_sel == 1 ? g_R0 : g_R1);
    const int relu_in = (in_sel != 0);
    const int by = blockIdx.y;
    const int is_root = (by >= 2);
    const int ocol = is_root ? (by - 2) * 64 : by * 64;
    const float* W = (is_root ? Wroot : Wrel) + ocol;

    const int tid  = threadIdx.x;
    const int row0 = blockIdx.x * 128;

    // ---- stage A (128x128): load fp32, ReLU, split to bf16 hi/lo planes ----
    #pragma unroll
    for (int i = 0; i < 16; i++) {
        int f4 = tid + i * 256;
        int r = f4 >> 5, c4 = f4 & 31;
        float4 v = make_float4(0.f, 0.f, 0.f, 0.f);
        if (row0 + r < NN)
            v = *(const float4*)(X + (size_t)(row0 + r) * CC + c4 * 4);
        if (relu_in) {
            v.x = fmaxf(v.x, 0.f); v.y = fmaxf(v.y, 0.f);
            v.z = fmaxf(v.z, 0.f); v.w = fmaxf(v.w, 0.f);
        }
        unsigned h0, l0, h1, l1;
        split2_bf16(v.x, v.y, h0, l0);
        split2_bf16(v.z, v.w, h1, l1);
        ((uint2*)Ah)[r * 34 + c4] = make_uint2(h0, h1);
        ((uint2*)Al)[r * 34 + c4] = make_uint2(l0, l1);
    }
    // ---- stage B (128k x 64n) -> transposed split planes Bt[n][k] ----
    {
        int n  = tid & 63;          // output col within 64-slice
        int kq = tid >> 6;          // 0..3 -> k quad
        #pragma unroll
        for (int i = 0; i < 8; i++) {
            int k = i * 16 + kq * 4;
            float w0 = W[(size_t)(k    ) * CC + n];
            float w1 = W[(size_t)(k + 1) * CC + n];
            float w2 = W[(size_t)(k + 2) * CC + n];
            float w3 = W[(size_t)(k + 3) * CC + n];
            unsigned h0, l0, h1, l1;
            split2_bf16(w0, w1, h0, l0);
            split2_bf16(w2, w3, h1, l1);
            ((uint2*)Bh)[n * 34 + (k >> 2)] = make_uint2(h0, h1);
            ((uint2*)Bl)[n * 34 + (k >> 2)] = make_uint2(l0, l1);
        }
    }
    __syncthreads();

    const int lane = tid & 31;
    const int w    = tid >> 5;         // 0..7
    const int wm   = w >> 1;           // 0..3 : rows wm*32
    const int wn   = w & 1;            // 0..1 : cols wn*32
    const int gr   = lane >> 2;        // 0..7
    const int tg   = lane & 3;         // 0..3

    float4 acc[2][4];
    #pragma unroll
    for (int mt = 0; mt < 2; mt++)
        #pragma unroll
        for (int nt = 0; nt < 4; nt++)
            acc[mt][nt] = make_float4(0.f, 0.f, 0.f, 0.f);

    #pragma unroll 4
    for (int ks = 0; ks < 8; ks++) {
        const int kw = ks * 8;                 // word offset within row
        unsigned ah[2][4], al[2][4], bh[4][2], bl[4][2];
        #pragma unroll
        for (int mt = 0; mt < 2; mt++) {
            int r = wm * 32 + mt * 16 + gr;
            int i0 = r * AW + kw + tg;
            int i1 = (r + 8) * AW + kw + tg;
            ah[mt][0] = Ah[i0];     ah[mt][1] = Ah[i1];
            ah[mt][2] = Ah[i0 + 4]; ah[mt][3] = Ah[i1 + 4];
            al[mt][0] = Al[i0];     al[mt][1] = Al[i1];
            al[mt][2] = Al[i0 + 4]; al[mt][3] = Al[i1 + 4];
        }
        #pragma unroll
        for (int nt = 0; nt < 4; nt++) {
            int n = wn * 32 + nt * 8 + gr;
            int j0 = n * BW + kw + tg;
            bh[nt][0] = Bh[j0]; bh[nt][1] = Bh[j0 + 4];
            bl[nt][0] = Bl[j0]; bl[nt][1] = Bl[j0 + 4];
        }
        #pragma unroll
        for (int mt = 0; mt < 2; mt++)
            #pragma unroll
            for (int nt = 0; nt < 4; nt++) {
                mma_bf16(acc[mt][nt], ah[mt], bl[nt]);   // small terms first
                mma_bf16(acc[mt][nt], al[mt], bh[nt]);
                mma_bf16(acc[mt][nt], ah[mt], bh[nt]);
            }
    }

    // ---- epilogue ----
    float* Rout = out_sel ? g_R1 : g_R0;
    #pragma unroll
    for (int mt = 0; mt < 2; mt++) {
        #pragma unroll
        for (int nt = 0; nt < 4; nt++) {
            int cl = wn * 32 + nt * 8 + tg * 2;
            int cg = ocol + cl;
            int r  = row0 + wm * 32 + mt * 16 + gr;
            if (is_root) {
                float b0 = __ldg(bias + cg), b1 = __ldg(bias + cg + 1);
                if (r < NN)
                    *(float2*)(Rout + (size_t)r * CC + cg) =
                        make_float2(acc[mt][nt].x + b0, acc[mt][nt].y + b1);
                if (r + 8 < NN)
                    *(float2*)(Rout + (size_t)(r + 8) * CC + cg) =
                        make_float2(acc[mt][nt].z + b0, acc[mt][nt].w + b1);
            } else {
                if (r < NN)
                    *(__half2*)(g_Yh + (size_t)r * CC + cg) =
                        __floats2half2_rn(acc[mt][nt].x, acc[mt][nt].y);
                if (r + 8 < NN)
                    *(__half2*)(g_Yh + (size_t)(r + 8) * CC + cg) =
                        __floats2half2_rn(acc[mt][nt].z, acc[mt][nt].w);
            }
        }
    }
}

// ---------------------------------------------------------------------------
// Aggregation: R[n] += sum_{e: dst=n} w_e * Yh[src_e]   (warp per node)
// Uniform LDG.128 edge broadcast (no shfl), x4 unroll -> 4 gathers in flight.
// ---------------------------------------------------------------------------
__global__ __launch_bounds__(256)
void k_agg(int out_sel) {
    float* R = out_sel ? g_R1 : g_R0;
    int gw   = (blockIdx.x * blockDim.x + threadIdx.x) >> 5;
    int lane = threadIdx.x & 31;
    if (gw >= NN) return;

    int deg = min(g_cnt[gw], CAP);
    float4 acc0 = *(float4*)(R + (size_t)gw * CC + lane * 4);
    float4 acc1 = make_float4(0.f, 0.f, 0.f, 0.f);
    const uint4* bk4 = (const uint4*)(g_bucket + (size_t)gw * CAP);

    int k = 0;
    for (; k + 4 <= deg; k += 4) {
        uint4 ea = __ldg(&bk4[(k >> 1)]);       // edges k, k+1 (uniform -> bcast)
        uint4 eb = __ldg(&bk4[(k >> 1) + 1]);   // edges k+2, k+3
        float w0 = __uint_as_float(ea.y), w1 = __uint_as_float(ea.w);
        float w2 = __uint_as_float(eb.y), w3 = __uint_as_float(eb.w);
        uint2 p0 = *(const uint2*)(g_Yh + (size_t)ea.x * CC + lane * 4);
        uint2 p1 = *(const uint2*)(g_Yh + (size_t)ea.z * CC + lane * 4);
        uint2 p2 = *(const uint2*)(g_Yh + (size_t)eb.x * CC + lane * 4);
        uint2 p3 = *(const uint2*)(g_Yh + (size_t)eb.z * CC + lane * 4);
        float2 a0 = __half22float2(*(const __half2*)&p0.x);
        float2 a1 = __half22float2(*(const __half2*)&p0.y);
        float2 b0 = __half22float2(*(const __half2*)&p1.x);
        float2 b1 = __half22float2(*(const __half2*)&p1.y);
        float2 c0 = __half22float2(*(const __half2*)&p2.x);
        float2 c1 = __half22float2(*(const __half2*)&p2.y);
        float2 d0 = __half22float2(*(const __half2*)&p3.x);
        float2 d1 = __half22float2(*(const __half2*)&p3.y);
        acc0.x += w0 * a0.x; acc0.y += w0 * a0.y; acc0.z += w0 * a1.x; acc0.w += w0 * a1.y;
        acc1.x += w1 * b0.x; acc1.y += w1 * b0.y; acc1.z += w1 * b1.x; acc1.w += w1 * b1.y;
        acc0.x += w2 * c0.x; acc0.y += w2 * c0.y; acc0.z += w2 * c1.x; acc0.w += w2 * c1.y;
        acc1.x += w3 * d0.x; acc1.y += w3 * d0.y; acc1.z += w3 * d1.x; acc1.w += w3 * d1.y;
    }
    const uint2* bk = (const uint2*)bk4;
    for (; k < deg; k++) {
        uint2 e = __ldg(&bk[k]);
        float wt = __uint_as_float(e.y);
        uint2 p  = *(const uint2*)(g_Yh + (size_t)e.x * CC + lane * 4);
        float2 a0 = __half22float2(*(const __half2*)&p.x);
        float2 a1 = __half22float2(*(const __half2*)&p.y);
        acc0.x += wt * a0.x; acc0.y += wt * a0.y;
        acc0.z += wt * a1.x; acc0.w += wt * a1.y;
    }
    acc0.x += acc1.x; acc0.y += acc1.y; acc0.z += acc1.z; acc0.w += acc1.w;
    *(float4*)(R + (size_t)gw * CC + lane * 4) = acc0;
}

// ---------------------------------------------------------------------------
// Head: logits = relu(R0) @ W_lin + b ; log_softmax  (warp per node)
// ---------------------------------------------------------------------------
__global__ __launch_bounds__(256)
void k_head(const float* __restrict__ W, const float* __restrict__ b,
            float* __restrict__ out) {
    __shared__ float Wt[OUTC][CC];
    __shared__ float bs[OUTC];
    for (int i = threadIdx.x; i < OUTC * CC; i += 256) {
        int c = i / CC, j = i % CC;
        Wt[c][j] = W[j * OUTC + c];
    }
    if (threadIdx.x < OUTC) bs[threadIdx.x] = b[threadIdx.x];
    __syncthreads();

    int gw   = (blockIdx.x * blockDim.x + threadIdx.x) >> 5;
    int lane = threadIdx.x & 31;
    if (gw >= NN) return;

    float4 x = *(const float4*)(g_R0 + (size_t)gw * CC + lane * 4);
    x.x = fmaxf(x.x, 0.f); x.y = fmaxf(x.y, 0.f);
    x.z = fmaxf(x.z, 0.f); x.w = fmaxf(x.w, 0.f);

    float p[OUTC];
    #pragma unroll
    for (int c = 0; c < OUTC; c++) {
        float4 wv = *(const float4*)&Wt[c][lane * 4];
        float t = x.x * wv.x + x.y * wv.y + x.z * wv.z + x.w * wv.w;
        #pragma unroll
        for (int off = 16; off > 0; off >>= 1)
            t += __shfl_xor_sync(0xffffffffu, t, off);
        p[c] = t + bs[c];
    }
    float mx = p[0];
    #pragma unroll
    for (int c = 1; c < OUTC; c++) mx = fmaxf(mx, p[c]);
    float se = 0.f;
    #pragma unroll
    for (int c = 0; c < OUTC; c++) se += expf(p[c] - mx);
    float lse = mx + logf(se);
    if (lane == 0) {
        #pragma unroll
        for (int c = 0; c < OUTC; c++)
            out[(size_t)gw * OUTC + c] = p[c] - lse;
    }
}

// ---------------------------------------------------------------------------
extern "C" void kernel_launch(void* const* d_in, const int* in_sizes, int n_in,
                              void* d_out, int out_size) {
    const float* x0  = (const float*)d_in[0];
    const int*   ei  = (const int*)  d_in[1];
    const float* ew  = (const float*)d_in[2];
    const float* W1r = (const float*)d_in[3];
    const float* b1  = (const float*)d_in[4];
    const float* W1o = (const float*)d_in[5];
    const float* W2r = (const float*)d_in[6];
    const float* b2  = (const float*)d_in[7];
    const float* W2o = (const float*)d_in[8];
    const float* W3r = (const float*)d_in[9];
    const float* b3  = (const float*)d_in[10];
    const float* W3o = (const float*)d_in[11];
    const float* Wl  = (const float*)d_in[12];
    const float* bl  = (const float*)d_in[13];
    float* out = (float*)d_out;

    cudaFuncSetAttribute(k_gemm_dual, cudaFuncAttributeMaxDynamicSharedMemorySize,
                         GEMM_SMEM);

    // edge bucketing (shared by all 3 layers)
    k_zero_cnt<<<(NN + 255) / 256, 256>>>();
    k_bucket<<<(EE + 255) / 256, 256>>>(ei, ei + EE, ew);

    dim3 ggrid((NN + 127) / 128, 4);   // 782 x 4

    // layer 1: x0 -> (Yh, R0); scatter into R0
    k_gemm_dual<<<ggrid, 256, GEMM_SMEM>>>(x0, 0, 0, W1r, W1o, b1);
    k_agg<<<NN / 8, 256>>>(0);
    // layer 2: relu(R0) -> (Yh, R1); scatter into R1
    k_gemm_dual<<<ggrid, 256, GEMM_SMEM>>>(nullptr, 1, 1, W2r, W2o, b2);
    k_agg<<<NN / 8, 256>>>(1);
    // layer 3: relu(R1) -> (Yh, R0); scatter into R0
    k_gemm_dual<<<ggrid, 256, GEMM_SMEM>>>(nullptr, 2, 0, W3r, W3o, b3);
    k_agg<<<NN / 8, 256>>>(0);
    // head
    k_head<<<NN / 8, 256>>>(Wl, bl, out);
}

// round 7
// speedup vs baseline: 1.0953x; 1.0953x over previous
#include <cuda_runtime.h>
#include <cuda_fp16.h>
#include <math.h>

#define NN 100000
#define EE 1600000
#define CC 128
#define CAP 96
#define OUTC 10

// ---- scratch (device globals: no allocation allowed) ----
__device__ __half g_Yh[(size_t)NN * CC];      // x @ W_rel, fp16 (25.6 MB)
__device__ float  g_R0[(size_t)NN * CC];      // ping
__device__ float  g_R1[(size_t)NN * CC];      // pong
__device__ int    g_cnt[NN];
__device__ __align__(16) uint2 g_bucket[(size_t)NN * CAP]; // {src, w-bits}

// ---------------------------------------------------------------------------
// Edge preprocessing: bucket edges by destination
// ---------------------------------------------------------------------------
__global__ void k_zero_cnt() {
    int i = blockIdx.x * blockDim.x + threadIdx.x;
    if (i < NN) g_cnt[i] = 0;
}

__global__ void k_bucket(const int* __restrict__ src, const int* __restrict__ dst,
                         const float* __restrict__ ew) {
    int e = blockIdx.x * blockDim.x + threadIdx.x;
    if (e >= EE) return;
    int d = dst[e];
    int s = atomicAdd(&g_cnt[d], 1);
    if (s < CAP)
        g_bucket[(size_t)d * CAP + s] = make_uint2((unsigned)src[e], __float_as_uint(ew[e]));
}

// ---------------------------------------------------------------------------
// 3x-bf16 tensor-core dual GEMM, split hoisted to staging, N=128 per CTA.
//   grid (782, 2): by=0 -> Y = act(X)@Wrel (fp16 out, all 128 cols)
//                  by=1 -> R = act(X)@Wroot + b (fp32 out, all 128 cols)
//   smem planes (bf16 pairs in u32 words):
//     Ah/Al: [128 rows][AW=68 words]   (row-major, K contiguous)
//     Bh/Bl: [128 nrows][BW=68 words]  (TRANSPOSED: n-major, K contiguous)
//   Mainloop: LDS.32 only, conflict-free (bank = 4*gr + tg + const), + HMMA.
//   3 mma passes: Ah*Bl + Al*Bh + Ah*Bh (dropped Al*Bl ~ 2^-16).
//   Warp tile 32(m) x 64(n): acc[2][8] float4.
// ---------------------------------------------------------------------------
#define AW 68
#define BW 68
#define A_WORDS (128 * AW)          // 8704
#define B_WORDS (128 * BW)          // 8704
#define GEMM_SMEM ((2 * A_WORDS + 2 * B_WORDS) * 4)   // 139264 B

// pack two consecutive-k fp32 values into bf16x2 hi + bf16x2 lo (residual)
__device__ __forceinline__ void split2_bf16(float x0, float x1,
                                            unsigned& h, unsigned& l) {
    asm("cvt.rn.bf16x2.f32 %0, %1, %2;" : "=r"(h) : "f"(x1), "f"(x0));
    float h0 = __uint_as_float(h << 16);
    float h1 = __uint_as_float(h & 0xffff0000u);
    float l0 = x0 - h0, l1 = x1 - h1;
    asm("cvt.rn.bf16x2.f32 %0, %1, %2;" : "=r"(l) : "f"(l1), "f"(l0));
}

__device__ __forceinline__ void mma_bf16(float4& d,
                                         const unsigned a[4], const unsigned b[2]) {
    asm volatile(
        "mma.sync.aligned.m16n8k16.row.col.f32.bf16.bf16.f32 "
        "{%0,%1,%2,%3}, {%4,%5,%6,%7}, {%8,%9}, {%0,%1,%2,%3};\n"
        : "+f"(d.x), "+f"(d.y), "+f"(d.z), "+f"(d.w)
        : "r"(a[0]), "r"(a[1]), "r"(a[2]), "r"(a[3]), "r"(b[0]), "r"(b[1]));
}

__global__ __launch_bounds__(256, 1)
void k_gemm_dual(const float* __restrict__ Xext,
                 int in_sel,              // 0: Xext, 1: g_R0 (ReLU), 2: g_R1 (ReLU)
                 int out_sel,             // 0: R=g_R0, 1: R=g_R1
                 const float* __restrict__ Wrel,
                 const float* __restrict__ Wroot,
                 const float* __restrict__ bias)
{
    extern __shared__ unsigned sw[];
    unsigned* Ah = sw;
    unsigned* Al = sw + A_WORDS;
    unsigned* Bh = sw + 2 * A_WORDS;
    unsigned* Bl = sw + 2 * A_WORDS + B_WORDS;

    const float* X = (in_sel == 0) ? Xext : (in_sel == 1 ? g_R0 : g_R1);
    const int relu_in = (in_sel != 0);
    const int is_root = (blockIdx.y != 0);
    const float* W = is_root ? Wroot : Wrel;

    const int tid  = threadIdx.x;
    const int row0 = blockIdx.x * 128;

    // ---- stage A (128x128): load fp32, ReLU, split to bf16 hi/lo planes ----
    #pragma unroll
    for (int i = 0; i < 16; i++) {
        int f4 = tid + i * 256;
        int r = f4 >> 5, c4 = f4 & 31;
        float4 v = make_float4(0.f, 0.f, 0.f, 0.f);
        if (row0 + r < NN)
            v = *(const float4*)(X + (size_t)(row0 + r) * CC + c4 * 4);
        if (relu_in) {
            v.x = fmaxf(v.x, 0.f); v.y = fmaxf(v.y, 0.f);
            v.z = fmaxf(v.z, 0.f); v.w = fmaxf(v.w, 0.f);
        }
        unsigned h0, l0, h1, l1;
        split2_bf16(v.x, v.y, h0, l0);
        split2_bf16(v.z, v.w, h1, l1);
        ((uint2*)Ah)[r * 34 + c4] = make_uint2(h0, h1);
        ((uint2*)Al)[r * 34 + c4] = make_uint2(l0, l1);
    }
    // ---- stage B (128k x 128n) -> transposed split planes Bt[n][k] ----
    {
        int n   = tid & 127;        // output col
        int kq8 = tid >> 7;         // 0..1
        #pragma unroll
        for (int i = 0; i < 16; i++) {
            int k = kq8 * 64 + i * 4;
            float w0 = W[(size_t)(k    ) * CC + n];
            float w1 = W[(size_t)(k + 1) * CC + n];
            float w2 = W[(size_t)(k + 2) * CC + n];
            float w3 = W[(size_t)(k + 3) * CC + n];
            unsigned h0, l0, h1, l1;
            split2_bf16(w0, w1, h0, l0);
            split2_bf16(w2, w3, h1, l1);
            ((uint2*)Bh)[n * 34 + (k >> 2)] = make_uint2(h0, h1);
            ((uint2*)Bl)[n * 34 + (k >> 2)] = make_uint2(l0, l1);
        }
    }
    __syncthreads();

    const int lane = tid & 31;
    const int w    = tid >> 5;         // 0..7
    const int wm   = w & 3;            // 0..3 : rows wm*32
    const int wn   = w >> 2;           // 0..1 : cols wn*64
    const int gr   = lane >> 2;        // 0..7
    const int tg   = lane & 3;         // 0..3

    float4 acc[2][8];
    #pragma unroll
    for (int mt = 0; mt < 2; mt++)
        #pragma unroll
        for (int nt = 0; nt < 8; nt++)
            acc[mt][nt] = make_float4(0.f, 0.f, 0.f, 0.f);

    #pragma unroll 2
    for (int ks = 0; ks < 8; ks++) {
        const int kw = ks * 8;
        unsigned ah[2][4], al[2][4], bh[8][2], bl[8][2];
        #pragma unroll
        for (int mt = 0; mt < 2; mt++) {
            int r = wm * 32 + mt * 16 + gr;
            int i0 = r * AW + kw + tg;
            int i1 = (r + 8) * AW + kw + tg;
            ah[mt][0] = Ah[i0];     ah[mt][1] = Ah[i1];
            ah[mt][2] = Ah[i0 + 4]; ah[mt][3] = Ah[i1 + 4];
            al[mt][0] = Al[i0];     al[mt][1] = Al[i1];
            al[mt][2] = Al[i0 + 4]; al[mt][3] = Al[i1 + 4];
        }
        #pragma unroll
        for (int nt = 0; nt < 8; nt++) {
            int n = wn * 64 + nt * 8 + gr;
            int j0 = n * BW + kw + tg;
            bh[nt][0] = Bh[j0]; bh[nt][1] = Bh[j0 + 4];
            bl[nt][0] = Bl[j0]; bl[nt][1] = Bl[j0 + 4];
        }
        #pragma unroll
        for (int mt = 0; mt < 2; mt++)
            #pragma unroll
            for (int nt = 0; nt < 8; nt++) {
                mma_bf16(acc[mt][nt], ah[mt], bl[nt]);   // small terms first
                mma_bf16(acc[mt][nt], al[mt], bh[nt]);
                mma_bf16(acc[mt][nt], ah[mt], bh[nt]);
            }
    }

    // ---- epilogue ----
    float* Rout = out_sel ? g_R1 : g_R0;
    #pragma unroll
    for (int mt = 0; mt < 2; mt++) {
        #pragma unroll
        for (int nt = 0; nt < 8; nt++) {
            int cg = wn * 64 + nt * 8 + tg * 2;
            int r  = row0 + wm * 32 + mt * 16 + gr;
            if (is_root) {
                float b0 = __ldg(bias + cg), b1 = __ldg(bias + cg + 1);
                if (r < NN)
                    *(float2*)(Rout + (size_t)r * CC + cg) =
                        make_float2(acc[mt][nt].x + b0, acc[mt][nt].y + b1);
                if (r + 8 < NN)
                    *(float2*)(Rout + (size_t)(r + 8) * CC + cg) =
                        make_float2(acc[mt][nt].z + b0, acc[mt][nt].w + b1);
            } else {
                if (r < NN)
                    *(__half2*)(g_Yh + (size_t)r * CC + cg) =
                        __floats2half2_rn(acc[mt][nt].x, acc[mt][nt].y);
                if (r + 8 < NN)
                    *(__half2*)(g_Yh + (size_t)(r + 8) * CC + cg) =
                        __floats2half2_rn(acc[mt][nt].z, acc[mt][nt].w);
            }
        }
    }
}

// ---------------------------------------------------------------------------
// Aggregation: R[n] += sum_{e: dst=n} w_e * Yh[src_e]   (warp per node)
// R5 version: shfl edge broadcast, fp16 gather, x2 unroll, dual accumulators.
// ---------------------------------------------------------------------------
__global__ __launch_bounds__(256)
void k_agg(int out_sel) {
    float* R = out_sel ? g_R1 : g_R0;
    int gw   = (blockIdx.x * blockDim.x + threadIdx.x) >> 5;
    int lane = threadIdx.x & 31;
    if (gw >= NN) return;

    int deg = min(g_cnt[gw], CAP);
    float4 acc0 = *(float4*)(R + (size_t)gw * CC + lane * 4);
    float4 acc1 = make_float4(0.f, 0.f, 0.f, 0.f);
    const uint2* bk = g_bucket + (size_t)gw * CAP;

    for (int base = 0; base < deg; base += 32) {
        int m = min(32, deg - base);
        uint2 e = make_uint2(0u, 0u);
        if (lane < m) e = bk[base + lane];
        int k = 0;
        for (; k + 2 <= m; k += 2) {
            int   s0 = __shfl_sync(0xffffffffu, (int)e.x, k);
            int   s1 = __shfl_sync(0xffffffffu, (int)e.x, k + 1);
            float w0 = __int_as_float(__shfl_sync(0xffffffffu, (int)e.y, k));
            float w1 = __int_as_float(__shfl_sync(0xffffffffu, (int)e.y, k + 1));
            uint2 p0 = *(const uint2*)(g_Yh + (size_t)s0 * CC + lane * 4);
            uint2 p1 = *(const uint2*)(g_Yh + (size_t)s1 * CC + lane * 4);
            float2 a0 = __half22float2(*(const __half2*)&p0.x);
            float2 a1 = __half22float2(*(const __half2*)&p0.y);
            float2 c0 = __half22float2(*(const __half2*)&p1.x);
            float2 c1 = __half22float2(*(const __half2*)&p1.y);
            acc0.x += w0 * a0.x; acc0.y += w0 * a0.y;
            acc0.z += w0 * a1.x; acc0.w += w0 * a1.y;
            acc1.x += w1 * c0.x; acc1.y += w1 * c0.y;
            acc1.z += w1 * c1.x; acc1.w += w1 * c1.y;
        }
        if (k < m) {
            int   s  = __shfl_sync(0xffffffffu, (int)e.x, k);
            float wt = __int_as_float(__shfl_sync(0xffffffffu, (int)e.y, k));
            uint2 p  = *(const uint2*)(g_Yh + (size_t)s * CC + lane * 4);
            float2 a0 = __half22float2(*(const __half2*)&p.x);
            float2 a1 = __half22float2(*(const __half2*)&p.y);
            acc0.x += wt * a0.x; acc0.y += wt * a0.y;
            acc0.z += wt * a1.x; acc0.w += wt * a1.y;
        }
    }
    acc0.x += acc1.x; acc0.y += acc1.y; acc0.z += acc1.z; acc0.w += acc1.w;
    *(float4*)(R + (size_t)gw * CC + lane * 4) = acc0;
}

// ---------------------------------------------------------------------------
// Head: logits = relu(R0) @ W_lin + b ; log_softmax  (warp per node)
// ---------------------------------------------------------------------------
__global__ __launch_bounds__(256)
void k_head(const float* __restrict__ W, const float* __restrict__ b,
            float* __restrict__ out) {
    __shared__ float Wt[OUTC][CC];
    __shared__ float bs[OUTC];
    for (int i = threadIdx.x; i < OUTC * CC; i += 256) {
        int c = i / CC, j = i % CC;
        Wt[c][j] = W[j * OUTC + c];
    }
    if (threadIdx.x < OUTC) bs[threadIdx.x] = b[threadIdx.x];
    __syncthreads();

    int gw   = (blockIdx.x * blockDim.x + threadIdx.x) >> 5;
    int lane = threadIdx.x & 31;
    if (gw >= NN) return;

    float4 x = *(const float4*)(g_R0 + (size_t)gw * CC + lane * 4);
    x.x = fmaxf(x.x, 0.f); x.y = fmaxf(x.y, 0.f);
    x.z = fmaxf(x.z, 0.f); x.w = fmaxf(x.w, 0.f);

    float p[OUTC];
    #pragma unroll
    for (int c = 0; c < OUTC; c++) {
        float4 wv = *(const float4*)&Wt[c][lane * 4];
        float t = x.x * wv.x + x.y * wv.y + x.z * wv.z + x.w * wv.w;
        #pragma unroll
        for (int off = 16; off > 0; off >>= 1)
            t += __shfl_xor_sync(0xffffffffu, t, off);
        p[c] = t + bs[c];
    }
    float mx = p[0];
    #pragma unroll
    for (int c = 1; c < OUTC; c++) mx = fmaxf(mx, p[c]);
    float se = 0.f;
    #pragma unroll
    for (int c = 0; c < OUTC; c++) se += expf(p[c] - mx);
    float lse = mx + logf(se);
    if (lane == 0) {
        #pragma unroll
        for (int c = 0; c < OUTC; c++)
            out[(size_t)gw * OUTC + c] = p[c] - lse;
    }
}

// ---------------------------------------------------------------------------
extern "C" void kernel_launch(void* const* d_in, const int* in_sizes, int n_in,
                              void* d_out, int out_size) {
    const float* x0  = (const float*)d_in[0];
    const int*   ei  = (const int*)  d_in[1];
    const float* ew  = (const float*)d_in[2];
    const float* W1r = (const float*)d_in[3];
    const float* b1  = (const float*)d_in[4];
    const float* W1o = (const float*)d_in[5];
    const float* W2r = (const float*)d_in[6];
    const float* b2  = (const float*)d_in[7];
    const float* W2o = (const float*)d_in[8];
    const float* W3r = (const float*)d_in[9];
    const float* b3  = (const float*)d_in[10];
    const float* W3o = (const float*)d_in[11];
    const float* Wl  = (const float*)d_in[12];
    const float* bl  = (const float*)d_in[13];
    float* out = (float*)d_out;

    cudaFuncSetAttribute(k_gemm_dual, cudaFuncAttributeMaxDynamicSharedMemorySize,
                         GEMM_SMEM);

    // edge bucketing (shared by all 3 layers)
    k_zero_cnt<<<(NN + 255) / 256, 256>>>();
    k_bucket<<<(EE + 255) / 256, 256>>>(ei, ei + EE, ew);

    dim3 ggrid((NN + 127) / 128, 2);   // 782 x 2

    // layer 1: x0 -> (Yh, R0); scatter into R0
    k_gemm_dual<<<ggrid, 256, GEMM_SMEM>>>(x0, 0, 0, W1r, W1o, b1);
    k_agg<<<NN / 8, 256>>>(0);
    // layer 2: relu(R0) -> (Yh, R1); scatter into R1
    k_gemm_dual<<<ggrid, 256, GEMM_SMEM>>>(nullptr, 1, 1, W2r, W2o, b2);
    k_agg<<<NN / 8, 256>>>(1);
    // layer 3: relu(R1) -> (Yh, R0); scatter into R0
    k_gemm_dual<<<ggrid, 256, GEMM_SMEM>>>(nullptr, 2, 0, W3r, W3o, b3);
    k_agg<<<NN / 8, 256>>>(0);
    // head
    k_head<<<NN / 8, 256>>>(Wl, bl, out);
}

// round 14
// speedup vs baseline: 1.4400x; 1.3147x over previous
#include <cuda_runtime.h>
#include <cuda_fp16.h>
#include <math.h>

#define NN 100000
#define EE 1600000
#define CC 128
#define CAP 96
#define OUTC 10

// ---- scratch (device globals: no allocation allowed) ----
__device__ __half g_Yh[(size_t)NN * CC];      // x @ W_rel, fp16 (25.6 MB)
__device__ float  g_R0[(size_t)NN * CC];      // ping
__device__ float  g_R1[(size_t)NN * CC];      // pong
__device__ int    g_cnt[NN];
__device__ __align__(16) uint2 g_bucket[(size_t)NN * CAP]; // {src, w-bits}

// ---------------------------------------------------------------------------
// Edge preprocessing
// ---------------------------------------------------------------------------
__global__ void k_zero_cnt(int base) {
    int i = base + blockIdx.x * blockDim.x + threadIdx.x;
    if (i < NN) g_cnt[i] = 0;
}

__global__ void k_bucket(const int* __restrict__ src, const int* __restrict__ dst,
                         const float* __restrict__ ew) {
    int e = blockIdx.x * blockDim.x + threadIdx.x;
    if (e >= EE) return;
    int d = dst[e];
    int s = atomicAdd(&g_cnt[d], 1);
    if (s < CAP)
        g_bucket[(size_t)d * CAP + s] = make_uint2((unsigned)src[e], __float_as_uint(ew[e]));
}

// ---------------------------------------------------------------------------
// Single-pass fp16 tensor-core dual GEMM (m16n8k16), N=128 per CTA.
//   grid (782, 2): by=0 -> Y = act(X)@Wrel (fp16 out, all 128 cols)
//                  by=1 -> R = act(X)@Wroot + b (fp32 out, all 128 cols)
//   smem planes (fp16 pairs in u32 words):
//     Ah: [128 rows][AW=68 words]   (row-major, K contiguous)
//     Bh: [128 nrows][BW=68 words]  (TRANSPOSED: n-major, K contiguous)
//   Mainloop: LDS.32 only, conflict-free (bank = 4*gr + tg + const), + HMMA.
//   Warp tile 32(m) x 64(n): acc[2][8] float4. 70KB smem -> 2 CTAs/SM.
// ---------------------------------------------------------------------------
#define AW 68
#define BW 68
#define A_WORDS (128 * AW)          // 8704
#define B_WORDS (128 * BW)          // 8704
#define GEMM_SMEM ((A_WORDS + B_WORDS) * 4)   // 69632 B

__device__ __forceinline__ unsigned pack_f16(float x0, float x1) {
    unsigned h;
    asm("cvt.rn.f16x2.f32 %0, %1, %2;" : "=r"(h) : "f"(x1), "f"(x0));
    return h;
}

__device__ __forceinline__ void mma_f16(float4& d,
                                        const unsigned a[4], const unsigned b[2]) {
    asm volatile(
        "mma.sync.aligned.m16n8k16.row.col.f32.f16.f16.f32 "
        "{%0,%1,%2,%3}, {%4,%5,%6,%7}, {%8,%9}, {%0,%1,%2,%3};\n"
        : "+f"(d.x), "+f"(d.y), "+f"(d.z), "+f"(d.w)
        : "r"(a[0]), "r"(a[1]), "r"(a[2]), "r"(a[3]), "r"(b[0]), "r"(b[1]));
}

__global__ __launch_bounds__(256, 2)
void k_gemm_dual(const float* __restrict__ Xext,
                 int in_sel,              // 0: Xext, 1: g_R0 (ReLU), 2: g_R1 (ReLU)
                 int out_sel,             // 0: R=g_R0, 1: R=g_R1
                 const float* __restrict__ Wrel,
                 const float* __restrict__ Wroot,
                 const float* __restrict__ bias)
{
    extern __shared__ unsigned sw[];
    unsigned* Ah = sw;
    unsigned* Bh = sw + A_WORDS;

    const float* X = (in_sel == 0) ? Xext : (in_sel == 1 ? g_R0 : g_R1);
    const int relu_in = (in_sel != 0);
    const int is_root = (blockIdx.y != 0);
    const float* W = is_root ? Wroot : Wrel;

    const int tid  = threadIdx.x;
    const int row0 = blockIdx.x * 128;

    // ---- stage A (128x128): load fp32, ReLU, pack fp16 ----
    #pragma unroll
    for (int i = 0; i < 16; i++) {
        int f4 = tid + i * 256;
        int r = f4 >> 5, c4 = f4 & 31;
        float4 v = make_float4(0.f, 0.f, 0.f, 0.f);
        if (row0 + r < NN)
            v = *(const float4*)(X + (size_t)(row0 + r) * CC + c4 * 4);
        if (relu_in) {
            v.x = fmaxf(v.x, 0.f); v.y = fmaxf(v.y, 0.f);
            v.z = fmaxf(v.z, 0.f); v.w = fmaxf(v.w, 0.f);
        }
        ((uint2*)Ah)[r * 34 + c4] =
            make_uint2(pack_f16(v.x, v.y), pack_f16(v.z, v.w));
    }
    // ---- stage B (128k x 128n) -> transposed fp16 plane Bt[n][k] ----
    {
        int n   = tid & 127;        // output col
        int kq8 = tid >> 7;         // 0..1
        #pragma unroll
        for (int i = 0; i < 16; i++) {
            int k = kq8 * 64 + i * 4;
            float w0 = W[(size_t)(k    ) * CC + n];
            float w1 = W[(size_t)(k + 1) * CC + n];
            float w2 = W[(size_t)(k + 2) * CC + n];
            float w3 = W[(size_t)(k + 3) * CC + n];
            ((uint2*)Bh)[n * 34 + (k >> 2)] =
                make_uint2(pack_f16(w0, w1), pack_f16(w2, w3));
        }
    }
    __syncthreads();

    const int lane = tid & 31;
    const int w    = tid >> 5;         // 0..7
    const int wm   = w & 3;            // 0..3 : rows wm*32
    const int wn   = w >> 2;           // 0..1 : cols wn*64
    const int gr   = lane >> 2;        // 0..7
    const int tg   = lane & 3;         // 0..3

    float4 acc[2][8];
    #pragma unroll
    for (int mt = 0; mt < 2; mt++)
        #pragma unroll
        for (int nt = 0; nt < 8; nt++)
            acc[mt][nt] = make_float4(0.f, 0.f, 0.f, 0.f);

    #pragma unroll
    for (int ks = 0; ks < 8; ks++) {
        const int kw = ks * 8;
        unsigned ah[2][4], bh[8][2];
        #pragma unroll
        for (int mt = 0; mt < 2; mt++) {
            int r = wm * 32 + mt * 16 + gr;
            int i0 = r * AW + kw + tg;
            int i1 = (r + 8) * AW + kw + tg;
            ah[mt][0] = Ah[i0];     ah[mt][1] = Ah[i1];
            ah[mt][2] = Ah[i0 + 4]; ah[mt][3] = Ah[i1 + 4];
        }
        #pragma unroll
        for (int nt = 0; nt < 8; nt++) {
            int n = wn * 64 + nt * 8 + gr;
            int j0 = n * BW + kw + tg;
            bh[nt][0] = Bh[j0]; bh[nt][1] = Bh[j0 + 4];
        }
        #pragma unroll
        for (int mt = 0; mt < 2; mt++)
            #pragma unroll
            for (int nt = 0; nt < 8; nt++)
                mma_f16(acc[mt][nt], ah[mt], bh[nt]);
    }

    // ---- epilogue ----
    float* Rout = out_sel ? g_R1 : g_R0;
    #pragma unroll
    for (int mt = 0; mt < 2; mt++) {
        #pragma unroll
        for (int nt = 0; nt < 8; nt++) {
            int cg = wn * 64 + nt * 8 + tg * 2;
            int r  = row0 + wm * 32 + mt * 16 + gr;
            if (is_root) {
                float b0 = __ldg(bias + cg), b1 = __ldg(bias + cg + 1);
                if (r < NN)
                    *(float2*)(Rout + (size_t)r * CC + cg) =
                        make_float2(acc[mt][nt].x + b0, acc[mt][nt].y + b1);
                if (r + 8 < NN)
                    *(float2*)(Rout + (size_t)(r + 8) * CC + cg) =
                        make_float2(acc[mt][nt].z + b0, acc[mt][nt].w + b1);
            } else {
                if (r < NN)
                    *(__half2*)(g_Yh + (size_t)r * CC + cg) =
                        __floats2half2_rn(acc[mt][nt].x, acc[mt][nt].y);
                if (r + 8 < NN)
                    *(__half2*)(g_Yh + (size_t)(r + 8) * CC + cg) =
                        __floats2half2_rn(acc[mt][nt].z, acc[mt][nt].w);
            }
        }
    }
}

// ---------------------------------------------------------------------------
// Aggregation (R5-proven): shfl edge broadcast, fp16 gather, x2 unroll.
// ---------------------------------------------------------------------------
__global__ __launch_bounds__(256)
void k_agg(int out_sel) {
    float* R = out_sel ? g_R1 : g_R0;
    int gw   = (blockIdx.x * blockDim.x + threadIdx.x) >> 5;
    int lane = threadIdx.x & 31;
    if (gw >= NN) return;

    int deg = min(g_cnt[gw], CAP);
    float4 acc0 = *(float4*)(R + (size_t)gw * CC + lane * 4);
    float4 acc1 = make_float4(0.f, 0.f, 0.f, 0.f);
    const uint2* bk = g_bucket + (size_t)gw * CAP;

    for (int base = 0; base < deg; base += 32) {
        int m = min(32, deg - base);
        uint2 e = make_uint2(0u, 0u);
        if (lane < m) e = bk[base + lane];
        int k = 0;
        for (; k + 2 <= m; k += 2) {
            int   s0 = __shfl_sync(0xffffffffu, (int)e.x, k);
            int   s1 = __shfl_sync(0xffffffffu, (int)e.x, k + 1);
            float w0 = __int_as_float(__shfl_sync(0xffffffffu, (int)e.y, k));
            float w1 = __int_as_float(__shfl_sync(0xffffffffu, (int)e.y, k + 1));
            uint2 p0 = *(const uint2*)(g_Yh + (size_t)s0 * CC + lane * 4);
            uint2 p1 = *(const uint2*)(g_Yh + (size_t)s1 * CC + lane * 4);
            float2 a0 = __half22float2(*(const __half2*)&p0.x);
            float2 a1 = __half22float2(*(const __half2*)&p0.y);
            float2 c0 = __half22float2(*(const __half2*)&p1.x);
            float2 c1 = __half22float2(*(const __half2*)&p1.y);
            acc0.x += w0 * a0.x; acc0.y += w0 * a0.y;
            acc0.z += w0 * a1.x; acc0.w += w0 * a1.y;
            acc1.x += w1 * c0.x; acc1.y += w1 * c0.y;
            acc1.z += w1 * c1.x; acc1.w += w1 * c1.y;
        }
        if (k < m) {
            int   s  = __shfl_sync(0xffffffffu, (int)e.x, k);
            float wt = __int_as_float(__shfl_sync(0xffffffffu, (int)e.y, k));
            uint2 p  = *(const uint2*)(g_Yh + (size_t)s * CC + lane * 4);
            float2 a0 = __half22float2(*(const __half2*)&p.x);
            float2 a1 = __half22float2(*(const __half2*)&p.y);
            acc0.x += wt * a0.x; acc0.y += wt * a0.y;
            acc0.z += wt * a1.x; acc0.w += wt * a1.y;
        }
    }
    acc0.x += acc1.x; acc0.y += acc1.y; acc0.z += acc1.z; acc0.w += acc1.w;
    *(float4*)(R + (size_t)gw * CC + lane * 4) = acc0;
}

// ---------------------------------------------------------------------------
// Head: logits = relu(R0) @ W_lin + b ; log_softmax  (warp per node)
// ---------------------------------------------------------------------------
__global__ __launch_bounds__(256)
void k_head(const float* __restrict__ W, const float* __restrict__ b,
            float* __restrict__ out) {
    __shared__ float Wt[OUTC][CC];
    __shared__ float bs[OUTC];
    for (int i = threadIdx.x; i < OUTC * CC; i += 256) {
        int c = i / CC, j = i % CC;
        Wt[c][j] = W[j * OUTC + c];
    }
    if (threadIdx.x < OUTC) bs[threadIdx.x] = b[threadIdx.x];
    __syncthreads();

    int gw   = (blockIdx.x * blockDim.x + threadIdx.x) >> 5;
    int lane = threadIdx.x & 31;
    if (gw >= NN) return;

    float4 x = *(const float4*)(g_R0 + (size_t)gw * CC + lane * 4);
    x.x = fmaxf(x.x, 0.f); x.y = fmaxf(x.y, 0.f);
    x.z = fmaxf(x.z, 0.f); x.w = fmaxf(x.w, 0.f);

    float p[OUTC];
    #pragma unroll
    for (int c = 0; c < OUTC; c++) {
        float4 wv = *(const float4*)&Wt[c][lane * 4];
        float t = x.x * wv.x + x.y * wv.y + x.z * wv.z + x.w * wv.w;
        #pragma unroll
        for (int off = 16; off > 0; off >>= 1)
            t += __shfl_xor_sync(0xffffffffu, t, off);
        p[c] = t + bs[c];
    }
    float mx = p[0];
    #pragma unroll
    for (int c = 1; c < OUTC; c++) mx = fmaxf(mx, p[c]);
    float se = 0.f;
    #pragma unroll
    for (int c = 0; c < OUTC; c++) se += expf(p[c] - mx);
    float lse = mx + logf(se);
    if (lane == 0) {
        #pragma unroll
        for (int c = 0; c < OUTC; c++)
            out[(size_t)gw * OUTC + c] = p[c] - lse;
    }
}

// ---------------------------------------------------------------------------
extern "C" void kernel_launch(void* const* d_in, const int* in_sizes, int n_in,
                              void* d_out, int out_size) {
    const float* x0  = (const float*)d_in[0];
    const int*   ei  = (const int*)  d_in[1];
    const float* ew  = (const float*)d_in[2];
    const float* W1r = (const float*)d_in[3];
    const float* b1  = (const float*)d_in[4];
    const float* W1o = (const float*)d_in[5];
    const float* W2r = (const float*)d_in[6];
    const float* b2  = (const float*)d_in[7];
    const float* W2o = (const float*)d_in[8];
    const float* W3r = (const float*)d_in[9];
    const float* b3  = (const float*)d_in[10];
    const float* W3o = (const float*)d_in[11];
    const float* Wl  = (const float*)d_in[12];
    const float* bl  = (const float*)d_in[13];
    float* out = (float*)d_out;

    cudaFuncSetAttribute(k_gemm_dual, cudaFuncAttributeMaxDynamicSharedMemorySize,
                         GEMM_SMEM);

    const int HALF = NN / 2;
    // two zero launches (keeps ncu -s 5 -c 1 capture on a GEMM launch)
    k_zero_cnt<<<(HALF + 255) / 256, 256>>>(0);
    k_zero_cnt<<<(NN - HALF + 255) / 256, 256>>>(HALF);
    k_bucket<<<(EE + 255) / 256, 256>>>(ei, ei + EE, ew);

    dim3 ggrid((NN + 127) / 128, 2);   // 782 x 2

    // layer 1: x0 -> (Yh, R0); scatter into R0
    k_gemm_dual<<<ggrid, 256, GEMM_SMEM>>>(x0, 0, 0, W1r, W1o, b1);
    k_agg<<<NN / 8, 256>>>(0);
    // layer 2: relu(R0) -> (Yh, R1); scatter into R1
    k_gemm_dual<<<ggrid, 256, GEMM_SMEM>>>(nullptr, 1, 1, W2r, W2o, b2);
    k_agg<<<NN / 8, 256>>>(1);
    // layer 3: relu(R1) -> (Yh, R0); scatter into R0
    k_gemm_dual<<<ggrid, 256, GEMM_SMEM>>>(nullptr, 2, 0, W3r, W3o, b3);
    k_agg<<<NN / 8, 256>>>(0);
    // head
    k_head<<<NN / 8, 256>>>(Wl, bl, out);
}

// round 15
// speedup vs baseline: 1.4409x; 1.0007x over previous
#include <cuda_runtime.h>
#include <cuda_fp16.h>
#include <math.h>

#define NN 100000
#define EE 1600000
#define CC 128
#define CAP 96
#define OUTC 10

// ---- scratch (device globals: no allocation allowed) ----
__device__ __half g_Yh[(size_t)NN * CC];      // x @ W_rel, fp16 (25.6 MB)
__device__ float  g_R0[(size_t)NN * CC];      // ping
__device__ float  g_R1[(size_t)NN * CC];      // pong
__device__ int    g_cnt[NN];
__device__ __align__(16) uint2 g_bucket[(size_t)NN * CAP]; // {src, w-bits}

// ---------------------------------------------------------------------------
// Edge preprocessing
// ---------------------------------------------------------------------------
__global__ void k_zero_cnt(int base) {
    int i = base + blockIdx.x * blockDim.x + threadIdx.x;
    if (i < NN) g_cnt[i] = 0;
}

__global__ void k_bucket(const int* __restrict__ src, const int* __restrict__ dst,
                         const float* __restrict__ ew) {
    int e = blockIdx.x * blockDim.x + threadIdx.x;
    if (e >= EE) return;
    int d = dst[e];
    int s = atomicAdd(&g_cnt[d], 1);
    if (s < CAP)
        g_bucket[(size_t)d * CAP + s] = make_uint2((unsigned)src[e], __float_as_uint(ew[e]));
}

// ---------------------------------------------------------------------------
// Single-pass fp16 tensor-core dual GEMM (m16n8k16), N=128 per CTA.
//   grid (782, 2): by=0 -> Y = act(X)@Wrel (fp16 out, all 128 cols)
//                  by=1 -> R = act(X)@Wroot + b (fp32 out, all 128 cols)
//   smem planes (fp16 pairs in u32 words):
//     Ah: [128 rows][AW=68 words]   (row-major, K contiguous)
//     Bh: [128 nrows][BW=68 words]  (TRANSPOSED: n-major, K contiguous)
//   Mainloop: LDS.32 only, conflict-free (bank = 4*gr + tg + const), + HMMA.
//   Warp tile 32(m) x 64(n): acc[2][8] float4. 70KB smem -> 2 CTAs/SM.
// ---------------------------------------------------------------------------
#define AW 68
#define BW 68
#define A_WORDS (128 * AW)          // 8704
#define B_WORDS (128 * BW)          // 8704
#define GEMM_SMEM ((A_WORDS + B_WORDS) * 4)   // 69632 B

__device__ __forceinline__ unsigned pack_f16(float x0, float x1) {
    unsigned h;
    asm("cvt.rn.f16x2.f32 %0, %1, %2;" : "=r"(h) : "f"(x1), "f"(x0));
    return h;
}

__device__ __forceinline__ void mma_f16(float4& d,
                                        const unsigned a[4], const unsigned b[2]) {
    asm volatile(
        "mma.sync.aligned.m16n8k16.row.col.f32.f16.f16.f32 "
        "{%0,%1,%2,%3}, {%4,%5,%6,%7}, {%8,%9}, {%0,%1,%2,%3};\n"
        : "+f"(d.x), "+f"(d.y), "+f"(d.z), "+f"(d.w)
        : "r"(a[0]), "r"(a[1]), "r"(a[2]), "r"(a[3]), "r"(b[0]), "r"(b[1]));
}

__global__ __launch_bounds__(256, 2)
void k_gemm_dual(const float* __restrict__ Xext,
                 int in_sel,              // 0: Xext, 1: g_R0 (ReLU), 2: g_R1 (ReLU)
                 int out_sel,             // 0: R=g_R0, 1: R=g_R1
                 const float* __restrict__ Wrel,
                 const float* __restrict__ Wroot,
                 const float* __restrict__ bias)
{
    extern __shared__ unsigned sw[];
    unsigned* Ah = sw;
    unsigned* Bh = sw + A_WORDS;

    const float* X = (in_sel == 0) ? Xext : (in_sel == 1 ? g_R0 : g_R1);
    const int relu_in = (in_sel != 0);
    const int is_root = (blockIdx.y != 0);
    const float* W = is_root ? Wroot : Wrel;

    const int tid  = threadIdx.x;
    const int row0 = blockIdx.x * 128;

    // ---- stage A (128x128): load fp32, ReLU, pack fp16 ----
    #pragma unroll
    for (int i = 0; i < 16; i++) {
        int f4 = tid + i * 256;
        int r = f4 >> 5, c4 = f4 & 31;
        float4 v = make_float4(0.f, 0.f, 0.f, 0.f);
        if (row0 + r < NN)
            v = *(const float4*)(X + (size_t)(row0 + r) * CC + c4 * 4);
        if (relu_in) {
            v.x = fmaxf(v.x, 0.f); v.y = fmaxf(v.y, 0.f);
            v.z = fmaxf(v.z, 0.f); v.w = fmaxf(v.w, 0.f);
        }
        ((uint2*)Ah)[r * 34 + c4] =
            make_uint2(pack_f16(v.x, v.y), pack_f16(v.z, v.w));
    }
    // ---- stage B (128k x 128n) -> transposed fp16 plane Bt[n][k] ----
    {
        int n   = tid & 127;        // output col
        int kq8 = tid >> 7;         // 0..1
        #pragma unroll
        for (int i = 0; i < 16; i++) {
            int k = kq8 * 64 + i * 4;
            float w0 = W[(size_t)(k    ) * CC + n];
            float w1 = W[(size_t)(k + 1) * CC + n];
            float w2 = W[(size_t)(k + 2) * CC + n];
            float w3 = W[(size_t)(k + 3) * CC + n];
            ((uint2*)Bh)[n * 34 + (k >> 2)] =
                make_uint2(pack_f16(w0, w1), pack_f16(w2, w3));
        }
    }
    __syncthreads();

    const int lane = tid & 31;
    const int w    = tid >> 5;         // 0..7
    const int wm   = w & 3;            // 0..3 : rows wm*32
    const int wn   = w >> 2;           // 0..1 : cols wn*64
    const int gr   = lane >> 2;        // 0..7
    const int tg   = lane & 3;         // 0..3

    float4 acc[2][8];
    #pragma unroll
    for (int mt = 0; mt < 2; mt++)
        #pragma unroll
        for (int nt = 0; nt < 8; nt++)
            acc[mt][nt] = make_float4(0.f, 0.f, 0.f, 0.f);

    #pragma unroll
    for (int ks = 0; ks < 8; ks++) {
        const int kw = ks * 8;
        unsigned ah[2][4], bh[8][2];
        #pragma unroll
        for (int mt = 0; mt < 2; mt++) {
            int r = wm * 32 + mt * 16 + gr;
            int i0 = r * AW + kw + tg;
            int i1 = (r + 8) * AW + kw + tg;
            ah[mt][0] = Ah[i0];     ah[mt][1] = Ah[i1];
            ah[mt][2] = Ah[i0 + 4]; ah[mt][3] = Ah[i1 + 4];
        }
        #pragma unroll
        for (int nt = 0; nt < 8; nt++) {
            int n = wn * 64 + nt * 8 + gr;
            int j0 = n * BW + kw + tg;
            bh[nt][0] = Bh[j0]; bh[nt][1] = Bh[j0 + 4];
        }
        #pragma unroll
        for (int mt = 0; mt < 2; mt++)
            #pragma unroll
            for (int nt = 0; nt < 8; nt++)
                mma_f16(acc[mt][nt], ah[mt], bh[nt]);
    }

    // ---- epilogue ----
    float* Rout = out_sel ? g_R1 : g_R0;
    #pragma unroll
    for (int mt = 0; mt < 2; mt++) {
        #pragma unroll
        for (int nt = 0; nt < 8; nt++) {
            int cg = wn * 64 + nt * 8 + tg * 2;
            int r  = row0 + wm * 32 + mt * 16 + gr;
            if (is_root) {
                float b0 = __ldg(bias + cg), b1 = __ldg(bias + cg + 1);
                if (r < NN)
                    *(float2*)(Rout + (size_t)r * CC + cg) =
                        make_float2(acc[mt][nt].x + b0, acc[mt][nt].y + b1);
                if (r + 8 < NN)
                    *(float2*)(Rout + (size_t)(r + 8) * CC + cg) =
                        make_float2(acc[mt][nt].z + b0, acc[mt][nt].w + b1);
            } else {
                if (r < NN)
                    *(__half2*)(g_Yh + (size_t)r * CC + cg) =
                        __floats2half2_rn(acc[mt][nt].x, acc[mt][nt].y);
                if (r + 8 < NN)
                    *(__half2*)(g_Yh + (size_t)(r + 8) * CC + cg) =
                        __floats2half2_rn(acc[mt][nt].z, acc[mt][nt].w);
            }
        }
    }
}

// ---------------------------------------------------------------------------
// Aggregation (R5-proven): shfl edge broadcast, fp16 gather, x2 unroll.
// ---------------------------------------------------------------------------
__global__ __launch_bounds__(256)
void k_agg(int out_sel) {
    float* R = out_sel ? g_R1 : g_R0;
    int gw   = (blockIdx.x * blockDim.x + threadIdx.x) >> 5;
    int lane = threadIdx.x & 31;
    if (gw >= NN) return;

    int deg = min(g_cnt[gw], CAP);
    float4 acc0 = *(float4*)(R + (size_t)gw * CC + lane * 4);
    float4 acc1 = make_float4(0.f, 0.f, 0.f, 0.f);
    const uint2* bk = g_bucket + (size_t)gw * CAP;

    for (int base = 0; base < deg; base += 32) {
        int m = min(32, deg - base);
        uint2 e = make_uint2(0u, 0u);
        if (lane < m) e = bk[base + lane];
        int k = 0;
        for (; k + 2 <= m; k += 2) {
            int   s0 = __shfl_sync(0xffffffffu, (int)e.x, k);
            int   s1 = __shfl_sync(0xffffffffu, (int)e.x, k + 1);
            float w0 = __int_as_float(__shfl_sync(0xffffffffu, (int)e.y, k));
            float w1 = __int_as_float(__shfl_sync(0xffffffffu, (int)e.y, k + 1));
            uint2 p0 = *(const uint2*)(g_Yh + (size_t)s0 * CC + lane * 4);
            uint2 p1 = *(const uint2*)(g_Yh + (size_t)s1 * CC + lane * 4);
            float2 a0 = __half22float2(*(const __half2*)&p0.x);
            float2 a1 = __half22float2(*(const __half2*)&p0.y);
            float2 c0 = __half22float2(*(const __half2*)&p1.x);
            float2 c1 = __half22float2(*(const __half2*)&p1.y);
            acc0.x += w0 * a0.x; acc0.y += w0 * a0.y;
            acc0.z += w0 * a1.x; acc0.w += w0 * a1.y;
            acc1.x += w1 * c0.x; acc1.y += w1 * c0.y;
            acc1.z += w1 * c1.x; acc1.w += w1 * c1.y;
        }
        if (k < m) {
            int   s  = __shfl_sync(0xffffffffu, (int)e.x, k);
            float wt = __int_as_float(__shfl_sync(0xffffffffu, (int)e.y, k));
            uint2 p  = *(const uint2*)(g_Yh + (size_t)s * CC + lane * 4);
            float2 a0 = __half22float2(*(const __half2*)&p.x);
            float2 a1 = __half22float2(*(const __half2*)&p.y);
            acc0.x += wt * a0.x; acc0.y += wt * a0.y;
            acc0.z += wt * a1.x; acc0.w += wt * a1.y;
        }
    }
    acc0.x += acc1.x; acc0.y += acc1.y; acc0.z += acc1.z; acc0.w += acc1.w;
    *(float4*)(R + (size_t)gw * CC + lane * 4) = acc0;
}

// ---------------------------------------------------------------------------
// Head: logits = relu(R0) @ W_lin + b ; log_softmax  (warp per node)
// ---------------------------------------------------------------------------
__global__ __launch_bounds__(256)
void k_head(const float* __restrict__ W, const float* __restrict__ b,
            float* __restrict__ out) {
    __shared__ float Wt[OUTC][CC];
    __shared__ float bs[OUTC];
    for (int i = threadIdx.x; i < OUTC * CC; i += 256) {
        int c = i / CC, j = i % CC;
        Wt[c][j] = W[j * OUTC + c];
    }
    if (threadIdx.x < OUTC) bs[threadIdx.x] = b[threadIdx.x];
    __syncthreads();

    int gw   = (blockIdx.x * blockDim.x + threadIdx.x) >> 5;
    int lane = threadIdx.x & 31;
    if (gw >= NN) return;

    float4 x = *(const float4*)(g_R0 + (size_t)gw * CC + lane * 4);
    x.x = fmaxf(x.x, 0.f); x.y = fmaxf(x.y, 0.f);
    x.z = fmaxf(x.z, 0.f); x.w = fmaxf(x.w, 0.f);

    float p[OUTC];
    #pragma unroll
    for (int c = 0; c < OUTC; c++) {
        float4 wv = *(const float4*)&Wt[c][lane * 4];
        float t = x.x * wv.x + x.y * wv.y + x.z * wv.z + x.w * wv.w;
        #pragma unroll
        for (int off = 16; off > 0; off >>= 1)
            t += __shfl_xor_sync(0xffffffffu, t, off);
        p[c] = t + bs[c];
    }
    float mx = p[0];
    #pragma unroll
    for (int c = 1; c < OUTC; c++) mx = fmaxf(mx, p[c]);
    float se = 0.f;
    #pragma unroll
    for (int c = 0; c < OUTC; c++) se += expf(p[c] - mx);
    float lse = mx + logf(se);
    if (lane == 0) {
        #pragma unroll
        for (int c = 0; c < OUTC; c++)
            out[(size_t)gw * OUTC + c] = p[c] - lse;
    }
}

// ---------------------------------------------------------------------------
extern "C" void kernel_launch(void* const* d_in, const int* in_sizes, int n_in,
                              void* d_out, int out_size) {
    const float* x0  = (const float*)d_in[0];
    const int*   ei  = (const int*)  d_in[1];
    const float* ew  = (const float*)d_in[2];
    const float* W1r = (const float*)d_in[3];
    const float* b1  = (const float*)d_in[4];
    const float* W1o = (const float*)d_in[5];
    const float* W2r = (const float*)d_in[6];
    const float* b2  = (const float*)d_in[7];
    const float* W2o = (const float*)d_in[8];
    const float* W3r = (const float*)d_in[9];
    const float* b3  = (const float*)d_in[10];
    const float* W3o = (const float*)d_in[11];
    const float* Wl  = (const float*)d_in[12];
    const float* bl  = (const float*)d_in[13];
    float* out = (float*)d_out;

    cudaFuncSetAttribute(k_gemm_dual, cudaFuncAttributeMaxDynamicSharedMemorySize,
                         GEMM_SMEM);

    const int HALF = NN / 2;
    // two zero launches (keeps ncu -s 5 -c 1 capture on a GEMM launch)
    k_zero_cnt<<<(HALF + 255) / 256, 256>>>(0);
    k_zero_cnt<<<(NN - HALF + 255) / 256, 256>>>(HALF);
    k_bucket<<<(EE + 255) / 256, 256>>>(ei, ei + EE, ew);

    dim3 ggrid((NN + 127) / 128, 2);   // 782 x 2

    // layer 1: x0 -> (Yh, R0); scatter into R0
    k_gemm_dual<<<ggrid, 256, GEMM_SMEM>>>(x0, 0, 0, W1r, W1o, b1);
    k_agg<<<NN / 8, 256>>>(0);
    // layer 2: relu(R0) -> (Yh, R1); scatter into R1
    k_gemm_dual<<<ggrid, 256, GEMM_SMEM>>>(nullptr, 1, 1, W2r, W2o, b2);
    k_agg<<<NN / 8, 256>>>(1);
    // layer 3: relu(R1) -> (Yh, R0); scatter into R0
    k_gemm_dual<<<ggrid, 256, GEMM_SMEM>>>(nullptr, 2, 0, W3r, W3o, b3);
    k_agg<<<NN / 8, 256>>>(0);
    // head
    k_head<<<NN / 8, 256>>>(Wl, bl, out);
}